// round 1
// baseline (speedup 1.0000x reference)
#include <cuda_runtime.h>
#include <math.h>

// Problem constants (fixed by setup_inputs)
#define N_NODES 4096
#define F_IN    512
#define NH      8
#define HC      64
#define D1      512     // NH*HC
#define NC2     16
#define MAXDEG  128

// ---------------- device scratch (no allocations allowed) ----------------
__device__ float g_h1[N_NODES * D1];      // x @ W1            [N, 512]
__device__ float g_asrc1[N_NODES * NH];   // per-node src score [N, 8]
__device__ float g_adst1[N_NODES * NH];   // per-node dst score [N, 8]
__device__ int   g_col[N_NODES * MAXDEG]; // neighbor lists (row-wise, incl self loop)
__device__ int   g_deg[N_NODES];
__device__ float g_e1[N_NODES * D1];      // elu(attn1_out + b1)
__device__ float g_h2[N_NODES * NC2];     // e1 @ W2           [N, 16]
__device__ float g_a2s[N_NODES];
__device__ float g_a2d[N_NODES];

// ---------------- K1: adj row -> neighbor list (with self loop) ----------------
__global__ void build_adj_kernel(const float* __restrict__ adj) {
    int i = blockIdx.x;
    __shared__ int cnt;
    if (threadIdx.x == 0) cnt = 0;
    __syncthreads();
    const float* row = adj + (size_t)i * N_NODES;
    for (int j = threadIdx.x; j < N_NODES; j += blockDim.x) {
        // _add_self_loops sets diag to 1; original adj values are 0/1
        if (row[j] != 0.0f || j == i) {
            int p = atomicAdd(&cnt, 1);
            if (p < MAXDEG) g_col[i * MAXDEG + p] = j;
        }
    }
    __syncthreads();
    if (threadIdx.x == 0) g_deg[i] = cnt < MAXDEG ? cnt : MAXDEG;
}

// ---------------- K2: GEMM1 h1 = x @ W1  (M=4096, N=512, K=512, fp32) ----------------
#define BM 64
#define BN 64
#define BK 16
__global__ void gemm1_kernel(const float* __restrict__ x, const float* __restrict__ W) {
    __shared__ float As[BK][BM];
    __shared__ float Bs[BK][BN];
    int bm = blockIdx.y * BM;
    int bn = blockIdx.x * BN;
    int tid = threadIdx.x;           // 256 threads
    int tr = tid >> 4;               // 0..15
    int tc = tid & 15;               // 0..15
    float acc[4][4];
    #pragma unroll
    for (int u = 0; u < 4; u++)
        #pragma unroll
        for (int v = 0; v < 4; v++) acc[u][v] = 0.0f;

    for (int k0 = 0; k0 < F_IN; k0 += BK) {
        #pragma unroll
        for (int t = tid; t < BM * BK; t += 256) {
            int m = t >> 4, k = t & 15;
            As[k][m] = x[(size_t)(bm + m) * F_IN + k0 + k];
        }
        #pragma unroll
        for (int t = tid; t < BK * BN; t += 256) {
            int k = t >> 6, n = t & 63;
            Bs[k][n] = W[(size_t)(k0 + k) * D1 + bn + n];
        }
        __syncthreads();
        #pragma unroll
        for (int k = 0; k < BK; k++) {
            float a[4], b[4];
            #pragma unroll
            for (int u = 0; u < 4; u++) a[u] = As[k][tr * 4 + u];
            #pragma unroll
            for (int v = 0; v < 4; v++) b[v] = Bs[k][tc * 4 + v];
            #pragma unroll
            for (int u = 0; u < 4; u++)
                #pragma unroll
                for (int v = 0; v < 4; v++) acc[u][v] = fmaf(a[u], b[v], acc[u][v]);
        }
        __syncthreads();
    }
    #pragma unroll
    for (int u = 0; u < 4; u++)
        #pragma unroll
        for (int v = 0; v < 4; v++)
            g_h1[(size_t)(bm + tr * 4 + u) * D1 + bn + tc * 4 + v] = acc[u][v];
}

// ---------------- K3: per-node attention scores (layer 1) ----------------
// one warp per (node, head): dot of h1[n, h*64 : h*64+64] with att_src / att_dst
__global__ void scores1_kernel(const float* __restrict__ att_src,
                               const float* __restrict__ att_dst) {
    int gw = (blockIdx.x * blockDim.x + threadIdx.x) >> 5;
    int lane = threadIdx.x & 31;
    if (gw >= N_NODES * NH) return;
    int n = gw >> 3, h = gw & 7;
    const float* hp = g_h1 + (size_t)n * D1 + h * HC;
    float s = 0.0f, d = 0.0f;
    #pragma unroll
    for (int c = lane; c < HC; c += 32) {
        float v = hp[c];
        s = fmaf(v, att_src[h * HC + c], s);
        d = fmaf(v, att_dst[h * HC + c], d);
    }
    #pragma unroll
    for (int o = 16; o; o >>= 1) {
        s += __shfl_xor_sync(0xffffffffu, s, o);
        d += __shfl_xor_sync(0xffffffffu, d, o);
    }
    if (lane == 0) {
        g_asrc1[n * NH + h] = s;
        g_adst1[n * NH + h] = d;
    }
}

// ---------------- K4: layer-1 sparse attention + bias + ELU ----------------
// block per row i; warp w handles head w (8 warps)
__global__ void attn1_kernel(const float* __restrict__ b1) {
    int i = blockIdx.x;
    int tid = threadIdx.x;
    int h = tid >> 5;       // warp id = head
    int lane = tid & 31;

    __shared__ int   nbr[MAXDEG];
    __shared__ float wgt[NH][MAXDEG];
    __shared__ int   s_deg;
    if (tid == 0) s_deg = g_deg[i];
    __syncthreads();
    int deg = s_deg;
    for (int j = tid; j < deg; j += 256) nbr[j] = g_col[i * MAXDEG + j];
    __syncthreads();

    float adst = g_adst1[i * NH + h];

    // pass 1: leaky-relu scores + max
    float m = -1e30f;
    for (int j = lane; j < deg; j += 32) {
        float a = g_asrc1[nbr[j] * NH + h] + adst;
        a = a > 0.0f ? a : 0.2f * a;
        wgt[h][j] = a;
        m = fmaxf(m, a);
    }
    #pragma unroll
    for (int o = 16; o; o >>= 1) m = fmaxf(m, __shfl_xor_sync(0xffffffffu, m, o));

    // pass 2: exp + sum
    float s = 0.0f;
    for (int j = lane; j < deg; j += 32) {
        float e = expf(wgt[h][j] - m);
        wgt[h][j] = e;
        s += e;
    }
    #pragma unroll
    for (int o = 16; o; o >>= 1) s += __shfl_xor_sync(0xffffffffu, s, o);
    float inv = 1.0f / s;
    __syncwarp();

    // accumulate: lane owns channels (lane) and (lane+32) of this head
    float acc0 = 0.0f, acc1 = 0.0f;
    #pragma unroll 4
    for (int j = 0; j < deg; j++) {
        float w = wgt[h][j];
        const float* hp = g_h1 + (size_t)nbr[j] * D1 + h * HC;
        acc0 = fmaf(w, hp[lane], acc0);
        acc1 = fmaf(w, hp[lane + 32], acc1);
    }
    acc0 *= inv;
    acc1 *= inv;
    int c0 = h * HC + lane;
    float y0 = acc0 + b1[c0];
    float y1 = acc1 + b1[c0 + 32];
    g_e1[(size_t)i * D1 + c0]      = y0 > 0.0f ? y0 : expm1f(y0);
    g_e1[(size_t)i * D1 + c0 + 32] = y1 > 0.0f ? y1 : expm1f(y1);
}

// ---------------- K5: GEMM2 h2 = e1 @ W2  (M=4096, N=16, K=512) ----------------
// block handles 16 rows; thread (r,c) computes one output; W2 staged in smem
__global__ void gemm2_kernel(const float* __restrict__ W2) {
    __shared__ float sW[D1 * NC2];   // 32KB
    int tid = threadIdx.x;           // 256
    int r0 = blockIdx.x * 16;
    for (int t = tid; t < D1 * NC2; t += 256) sW[t] = W2[t];
    __syncthreads();
    int r = tid >> 4, c = tid & 15;
    const float* e = g_e1 + (size_t)(r0 + r) * D1;
    float acc = 0.0f;
    #pragma unroll 8
    for (int k = 0; k < D1; k++) acc = fmaf(e[k], sW[k * NC2 + c], acc);
    g_h2[(size_t)(r0 + r) * NC2 + c] = acc;
}

// ---------------- K6: per-node scores (layer 2, H=1, C=16) ----------------
__global__ void scores2_kernel(const float* __restrict__ as2,
                               const float* __restrict__ ad2) {
    int n = blockIdx.x * blockDim.x + threadIdx.x;
    if (n >= N_NODES) return;
    float s = 0.0f, d = 0.0f;
    #pragma unroll
    for (int c = 0; c < NC2; c++) {
        float v = g_h2[n * NC2 + c];
        s = fmaf(v, as2[c], s);
        d = fmaf(v, ad2[c], d);
    }
    g_a2s[n] = s;
    g_a2d[n] = d;
}

// ---------------- K7: layer-2 sparse attention -> output ----------------
// one warp per row
__global__ void attn2_kernel(const float* __restrict__ b2, float* __restrict__ out) {
    int i = blockIdx.x;
    int lane = threadIdx.x;

    __shared__ int   nbr[MAXDEG];
    __shared__ float wgt[MAXDEG];
    int deg = g_deg[i];
    for (int j = lane; j < deg; j += 32) nbr[j] = g_col[i * MAXDEG + j];
    __syncwarp();

    float adst = g_a2d[i];
    float m = -1e30f;
    for (int j = lane; j < deg; j += 32) {
        float a = g_a2s[nbr[j]] + adst;
        a = a > 0.0f ? a : 0.2f * a;
        wgt[j] = a;
        m = fmaxf(m, a);
    }
    #pragma unroll
    for (int o = 16; o; o >>= 1) m = fmaxf(m, __shfl_xor_sync(0xffffffffu, m, o));
    float s = 0.0f;
    for (int j = lane; j < deg; j += 32) {
        float e = expf(wgt[j] - m);
        wgt[j] = e;
        s += e;
    }
    #pragma unroll
    for (int o = 16; o; o >>= 1) s += __shfl_xor_sync(0xffffffffu, s, o);
    float inv = 1.0f / s;
    __syncwarp();

    if (lane < NC2) {
        float acc = 0.0f;
        #pragma unroll 4
        for (int j = 0; j < deg; j++)
            acc = fmaf(wgt[j], g_h2[(size_t)nbr[j] * NC2 + lane], acc);
        out[i * NC2 + lane] = acc * inv + b2[lane];
    }
}

// ---------------- launch ----------------
extern "C" void kernel_launch(void* const* d_in, const int* in_sizes, int n_in,
                              void* d_out, int out_size) {
    const float* x   = (const float*)d_in[0];
    const float* adj = (const float*)d_in[1];
    const float* W1  = (const float*)d_in[2];
    const float* as1 = (const float*)d_in[3];
    const float* ad1 = (const float*)d_in[4];
    const float* b1  = (const float*)d_in[5];
    const float* W2  = (const float*)d_in[6];
    const float* as2 = (const float*)d_in[7];
    const float* ad2 = (const float*)d_in[8];
    const float* b2  = (const float*)d_in[9];
    float* out = (float*)d_out;

    build_adj_kernel<<<N_NODES, 256>>>(adj);

    dim3 g1(D1 / BN, N_NODES / BM);        // (8, 64)
    gemm1_kernel<<<g1, 256>>>(x, W1);

    scores1_kernel<<<(N_NODES * NH * 32) / 256, 256>>>(as1, ad1);
    attn1_kernel<<<N_NODES, 256>>>(b1);

    gemm2_kernel<<<N_NODES / 16, 256>>>(W2);
    scores2_kernel<<<N_NODES / 256, 256>>>(as2, ad2);
    attn2_kernel<<<N_NODES, 32>>>(b2, out);
}

// round 2
// speedup vs baseline: 1.6360x; 1.6360x over previous
#include <cuda_runtime.h>
#include <mma.h>
#include <math.h>

using namespace nvcuda;

// Problem constants (fixed by setup_inputs)
#define N_NODES 4096
#define F_IN    512
#define NH      8
#define HC      64
#define D1      512     // NH*HC
#define NC2     16
#define MAXDEG  128

// ---------------- device scratch ----------------
__device__ float g_h1[N_NODES * D1];      // x @ W1            [N, 512]
__device__ float g_asrc1[N_NODES * NH];
__device__ float g_adst1[N_NODES * NH];
__device__ int   g_col[N_NODES * MAXDEG];
__device__ int   g_deg[N_NODES];
__device__ float g_e1[N_NODES * D1];      // elu(attn1_out + b1)
__device__ float g_h2[N_NODES * NC2];
__device__ float g_a2s[N_NODES];
__device__ float g_a2d[N_NODES];

// ---------------- K1: adj row -> neighbor list (ballot-compacted) ----------------
__global__ void build_adj_kernel(const float* __restrict__ adj) {
    int i = blockIdx.x;
    int tid = threadIdx.x;
    int lane = tid & 31;
    __shared__ int cnt;
    if (tid == 0) cnt = 0;
    __syncthreads();
    const float4* row4 = (const float4*)(adj + (size_t)i * N_NODES);
    #pragma unroll
    for (int it = 0; it < N_NODES / (256 * 4); it++) {
        int idx = it * 256 + tid;
        float4 v = row4[idx];
        int j0 = idx * 4;
        #pragma unroll
        for (int e = 0; e < 4; e++) {
            float f = (e == 0) ? v.x : (e == 1) ? v.y : (e == 2) ? v.z : v.w;
            int j = j0 + e;
            bool p = (f != 0.0f) || (j == i);
            unsigned m = __ballot_sync(0xffffffffu, p);
            if (m) {
                int base = 0;
                if (lane == 0) base = atomicAdd(&cnt, __popc(m));
                base = __shfl_sync(0xffffffffu, base, 0);
                if (p) {
                    int pos = base + __popc(m & ((1u << lane) - 1u));
                    if (pos < MAXDEG) g_col[i * MAXDEG + pos] = j;
                }
            }
        }
    }
    __syncthreads();
    if (tid == 0) g_deg[i] = cnt < MAXDEG ? cnt : MAXDEG;
}

// ---------------- K2: GEMM1 h1 = x @ W1  (TF32 wmma, 128x128x32 tiles) ----------------
#define GBM 128
#define GBN 128
#define GBK 32
#define LDA (GBK + 4)    // 36 floats
#define LDB (GBN + 4)    // 132 floats

__global__ void __launch_bounds__(256) gemm1_tf32_kernel(const float* __restrict__ x,
                                                         const float* __restrict__ W) {
    __shared__ float As[GBM * LDA];
    __shared__ float Bs[GBK * LDB];
    int bm = blockIdx.y * GBM;
    int bn = blockIdx.x * GBN;
    int tid = threadIdx.x;
    int wid = tid >> 5;
    int wr = wid >> 1;   // 0..3  -> 32 rows each
    int wc = wid & 1;    // 0..1  -> 64 cols each

    wmma::fragment<wmma::accumulator, 16, 16, 8, float> acc[2][4];
    #pragma unroll
    for (int i = 0; i < 2; i++)
        #pragma unroll
        for (int j = 0; j < 4; j++) wmma::fill_fragment(acc[i][j], 0.0f);

    for (int k0 = 0; k0 < F_IN; k0 += GBK) {
        // stage A: 128 rows x 32 k  (1024 float4)
        #pragma unroll
        for (int t = tid; t < GBM * 8; t += 256) {
            int r = t >> 3, q = t & 7;
            float4 v = *(const float4*)&x[(size_t)(bm + r) * F_IN + k0 + q * 4];
            *(float4*)&As[r * LDA + q * 4] = v;
        }
        // stage B: 32 k x 128 cols (1024 float4)
        #pragma unroll
        for (int t = tid; t < GBK * 32; t += 256) {
            int r = t >> 5, q = t & 31;
            float4 v = *(const float4*)&W[(size_t)(k0 + r) * D1 + bn + q * 4];
            *(float4*)&Bs[r * LDB + q * 4] = v;
        }
        __syncthreads();
        #pragma unroll
        for (int ks = 0; ks < GBK / 8; ks++) {
            wmma::fragment<wmma::matrix_a, 16, 16, 8, wmma::precision::tf32, wmma::row_major> a[2];
            wmma::fragment<wmma::matrix_b, 16, 16, 8, wmma::precision::tf32, wmma::row_major> b[4];
            #pragma unroll
            for (int i = 0; i < 2; i++) {
                wmma::load_matrix_sync(a[i], &As[(wr * 32 + i * 16) * LDA + ks * 8], LDA);
                #pragma unroll
                for (int e = 0; e < a[i].num_elements; e++)
                    a[i].x[e] = wmma::__float_to_tf32(a[i].x[e]);
            }
            #pragma unroll
            for (int j = 0; j < 4; j++) {
                wmma::load_matrix_sync(b[j], &Bs[ks * 8 * LDB + wc * 64 + j * 16], LDB);
                #pragma unroll
                for (int e = 0; e < b[j].num_elements; e++)
                    b[j].x[e] = wmma::__float_to_tf32(b[j].x[e]);
            }
            #pragma unroll
            for (int i = 0; i < 2; i++)
                #pragma unroll
                for (int j = 0; j < 4; j++)
                    wmma::mma_sync(acc[i][j], a[i], b[j], acc[i][j]);
        }
        __syncthreads();
    }
    #pragma unroll
    for (int i = 0; i < 2; i++)
        #pragma unroll
        for (int j = 0; j < 4; j++)
            wmma::store_matrix_sync(&g_h1[(size_t)(bm + wr * 32 + i * 16) * D1 + bn + wc * 64 + j * 16],
                                    acc[i][j], D1, wmma::mem_row_major);
}

// ---------------- K3: per-node attention scores (layer 1) ----------------
__global__ void scores1_kernel(const float* __restrict__ att_src,
                               const float* __restrict__ att_dst) {
    int gw = (blockIdx.x * blockDim.x + threadIdx.x) >> 5;
    int lane = threadIdx.x & 31;
    if (gw >= N_NODES * NH) return;
    int n = gw >> 3, h = gw & 7;
    const float2* hp = (const float2*)(g_h1 + (size_t)n * D1 + h * HC);
    const float2* sp = (const float2*)(att_src + h * HC);
    const float2* dp = (const float2*)(att_dst + h * HC);
    float2 v = hp[lane];
    float2 sa = sp[lane];
    float2 da = dp[lane];
    float s = v.x * sa.x + v.y * sa.y;
    float d = v.x * da.x + v.y * da.y;
    #pragma unroll
    for (int o = 16; o; o >>= 1) {
        s += __shfl_xor_sync(0xffffffffu, s, o);
        d += __shfl_xor_sync(0xffffffffu, d, o);
    }
    if (lane == 0) {
        g_asrc1[n * NH + h] = s;
        g_adst1[n * NH + h] = d;
    }
}

// ---------------- K4: layer-1 sparse attention + bias + ELU ----------------
__global__ void attn1_kernel(const float* __restrict__ b1) {
    int i = blockIdx.x;
    int tid = threadIdx.x;
    int h = tid >> 5;
    int lane = tid & 31;

    __shared__ int   nbr[MAXDEG];
    __shared__ float wgt[NH][MAXDEG];
    __shared__ int   s_deg;
    if (tid == 0) s_deg = g_deg[i];
    __syncthreads();
    int deg = s_deg;
    for (int j = tid; j < deg; j += 256) nbr[j] = g_col[i * MAXDEG + j];
    __syncthreads();

    float adst = g_adst1[i * NH + h];

    float m = -1e30f;
    for (int j = lane; j < deg; j += 32) {
        float a = g_asrc1[nbr[j] * NH + h] + adst;
        a = a > 0.0f ? a : 0.2f * a;
        wgt[h][j] = a;
        m = fmaxf(m, a);
    }
    #pragma unroll
    for (int o = 16; o; o >>= 1) m = fmaxf(m, __shfl_xor_sync(0xffffffffu, m, o));

    float s = 0.0f;
    for (int j = lane; j < deg; j += 32) {
        float e = expf(wgt[h][j] - m);
        wgt[h][j] = e;
        s += e;
    }
    #pragma unroll
    for (int o = 16; o; o >>= 1) s += __shfl_xor_sync(0xffffffffu, s, o);
    float inv = 1.0f / s;
    __syncwarp();

    // each lane owns channels (2*lane, 2*lane+1): one LDG.64 per neighbor
    float accx = 0.0f, accy = 0.0f;
    #pragma unroll 4
    for (int j = 0; j < deg; j++) {
        float w = wgt[h][j];
        const float2* hp = (const float2*)(g_h1 + (size_t)nbr[j] * D1 + h * HC);
        float2 v = hp[lane];
        accx = fmaf(w, v.x, accx);
        accy = fmaf(w, v.y, accy);
    }
    accx *= inv;
    accy *= inv;
    int c0 = h * HC + lane * 2;
    float y0 = accx + b1[c0];
    float y1 = accy + b1[c0 + 1];
    g_e1[(size_t)i * D1 + c0]     = y0 > 0.0f ? y0 : expm1f(y0);
    g_e1[(size_t)i * D1 + c0 + 1] = y1 > 0.0f ? y1 : expm1f(y1);
}

// ---------------- K5: GEMM2 h2 = e1 @ W2  (warp-per-row split-K) ----------------
__global__ void gemm2_kernel(const float* __restrict__ W2) {
    __shared__ float sW[F_IN * 0 + D1 * 17];   // [512][17] padded -> conflict-free
    int tid = threadIdx.x;   // 256 threads = 8 warps
    int wid = tid >> 5;
    int lane = tid & 31;
    for (int t = tid; t < D1 * NC2; t += 256) {
        int k = t >> 4, c = t & 15;
        sW[k * 17 + c] = W2[t];
    }
    __syncthreads();

    int row = blockIdx.x * 8 + wid;
    const float* e = g_e1 + (size_t)row * D1;
    float p[NC2];
    #pragma unroll
    for (int c = 0; c < NC2; c++) p[c] = 0.0f;
    #pragma unroll 2
    for (int k = lane; k < D1; k += 32) {
        float v = e[k];
        const float* w = &sW[k * 17];
        #pragma unroll
        for (int c = 0; c < NC2; c++) p[c] = fmaf(v, w[c], p[c]);
    }
    #pragma unroll
    for (int c = 0; c < NC2; c++) {
        #pragma unroll
        for (int o = 16; o; o >>= 1) p[c] += __shfl_xor_sync(0xffffffffu, p[c], o);
    }
    if (lane == 0) {
        #pragma unroll
        for (int c = 0; c < NC2; c++) g_h2[(size_t)row * NC2 + c] = p[c];
    }
}

// ---------------- K6: per-node scores (layer 2) ----------------
__global__ void scores2_kernel(const float* __restrict__ as2,
                               const float* __restrict__ ad2) {
    int n = blockIdx.x * blockDim.x + threadIdx.x;
    if (n >= N_NODES) return;
    float s = 0.0f, d = 0.0f;
    #pragma unroll
    for (int c = 0; c < NC2; c++) {
        float v = g_h2[n * NC2 + c];
        s = fmaf(v, as2[c], s);
        d = fmaf(v, ad2[c], d);
    }
    g_a2s[n] = s;
    g_a2d[n] = d;
}

// ---------------- K7: layer-2 sparse attention -> output ----------------
__global__ void attn2_kernel(const float* __restrict__ b2, float* __restrict__ out) {
    int i = blockIdx.x;
    int lane = threadIdx.x;

    __shared__ int   nbr[MAXDEG];
    __shared__ float wgt[MAXDEG];
    int deg = g_deg[i];
    for (int j = lane; j < deg; j += 32) nbr[j] = g_col[i * MAXDEG + j];
    __syncwarp();

    float adst = g_a2d[i];
    float m = -1e30f;
    for (int j = lane; j < deg; j += 32) {
        float a = g_a2s[nbr[j]] + adst;
        a = a > 0.0f ? a : 0.2f * a;
        wgt[j] = a;
        m = fmaxf(m, a);
    }
    #pragma unroll
    for (int o = 16; o; o >>= 1) m = fmaxf(m, __shfl_xor_sync(0xffffffffu, m, o));
    float s = 0.0f;
    for (int j = lane; j < deg; j += 32) {
        float e = expf(wgt[j] - m);
        wgt[j] = e;
        s += e;
    }
    #pragma unroll
    for (int o = 16; o; o >>= 1) s += __shfl_xor_sync(0xffffffffu, s, o);
    float inv = 1.0f / s;
    __syncwarp();

    if (lane < NC2) {
        float acc = 0.0f;
        #pragma unroll 4
        for (int j = 0; j < deg; j++)
            acc = fmaf(wgt[j], g_h2[(size_t)nbr[j] * NC2 + lane], acc);
        out[i * NC2 + lane] = acc * inv + b2[lane];
    }
}

// ---------------- launch ----------------
extern "C" void kernel_launch(void* const* d_in, const int* in_sizes, int n_in,
                              void* d_out, int out_size) {
    const float* x   = (const float*)d_in[0];
    const float* adj = (const float*)d_in[1];
    const float* W1  = (const float*)d_in[2];
    const float* as1 = (const float*)d_in[3];
    const float* ad1 = (const float*)d_in[4];
    const float* b1  = (const float*)d_in[5];
    const float* W2  = (const float*)d_in[6];
    const float* as2 = (const float*)d_in[7];
    const float* ad2 = (const float*)d_in[8];
    const float* b2  = (const float*)d_in[9];
    float* out = (float*)d_out;

    // lazy-init side stream + events (created once, outside capture)
    static cudaStream_t s2 = 0;
    static cudaEvent_t evFork = 0, evJoin = 0;
    static bool init = false;
    if (!init) {
        if (cudaStreamCreateWithFlags(&s2, cudaStreamNonBlocking) != cudaSuccess) s2 = 0;
        if (cudaEventCreateWithFlags(&evFork, cudaEventDisableTiming) != cudaSuccess) evFork = 0;
        if (cudaEventCreateWithFlags(&evJoin, cudaEventDisableTiming) != cudaSuccess) evJoin = 0;
        if (!evFork || !evJoin) s2 = 0;
        init = true;
    }

    dim3 g1(D1 / GBN, N_NODES / GBM);   // (4, 32)

    if (s2) {
        // fork: build_adj runs concurrently with GEMM1 + scores1
        cudaEventRecord(evFork, 0);
        cudaStreamWaitEvent(s2, evFork, 0);
        build_adj_kernel<<<N_NODES, 256, 0, s2>>>(adj);
        gemm1_tf32_kernel<<<g1, 256>>>(x, W1);
        scores1_kernel<<<(N_NODES * NH * 32) / 256, 256>>>(as1, ad1);
        cudaEventRecord(evJoin, s2);
        cudaStreamWaitEvent(0, evJoin, 0);
    } else {
        build_adj_kernel<<<N_NODES, 256>>>(adj);
        gemm1_tf32_kernel<<<g1, 256>>>(x, W1);
        scores1_kernel<<<(N_NODES * NH * 32) / 256, 256>>>(as1, ad1);
    }

    attn1_kernel<<<N_NODES, 256>>>(b1);
    gemm2_kernel<<<N_NODES / 8, 256>>>(W2);
    scores2_kernel<<<N_NODES / 256, 256>>>(as2, ad2);
    attn2_kernel<<<N_NODES, 32>>>(b2, out);
}

// round 4
// speedup vs baseline: 1.7543x; 1.0723x over previous
#include <cuda_runtime.h>
#include <mma.h>
#include <math.h>

using namespace nvcuda;

#define N_NODES 4096
#define F_IN    512
#define NH      8
#define HC      64
#define D1      512
#define NC2     16
#define MAXDEG  128

// ---------------- device scratch ----------------
__device__ float g_h1[N_NODES * D1];
__device__ float g_asrc1[N_NODES * NH];
__device__ float g_adst1[N_NODES * NH];
__device__ int   g_col[N_NODES * MAXDEG];
__device__ int   g_deg[N_NODES];
__device__ float g_e1[N_NODES * D1];
__device__ float g_h2[N_NODES * NC2];
__device__ float g_a2s[N_NODES];
__device__ float g_a2d[N_NODES];

// ---------------- cp.async helpers ----------------
__device__ __forceinline__ void cp_async16(void* smem_dst, const void* gmem_src) {
    unsigned int s = (unsigned int)__cvta_generic_to_shared(smem_dst);
    asm volatile("cp.async.ca.shared.global [%0], [%1], 16;\n" :: "r"(s), "l"(gmem_src));
}
__device__ __forceinline__ void cp_commit() {
    asm volatile("cp.async.commit_group;\n");
}
template <int N>
__device__ __forceinline__ void cp_wait() {
    asm volatile("cp.async.wait_group %0;\n" :: "n"(N));
}

// ---------------- K1: adj row -> neighbor list ----------------
__global__ void build_adj_kernel(const float* __restrict__ adj) {
    int i = blockIdx.x;
    int tid = threadIdx.x;
    int lane = tid & 31;
    __shared__ int cnt;
    if (tid == 0) cnt = 0;
    __syncthreads();
    const float4* row4 = (const float4*)(adj + (size_t)i * N_NODES);
    #pragma unroll
    for (int it = 0; it < N_NODES / (256 * 4); it++) {
        int idx = it * 256 + tid;
        float4 v = row4[idx];
        int j0 = idx * 4;
        #pragma unroll
        for (int e = 0; e < 4; e++) {
            float f = (e == 0) ? v.x : (e == 1) ? v.y : (e == 2) ? v.z : v.w;
            int j = j0 + e;
            bool p = (f != 0.0f) || (j == i);
            unsigned m = __ballot_sync(0xffffffffu, p);
            if (m) {
                int base = 0;
                if (lane == 0) base = atomicAdd(&cnt, __popc(m));
                base = __shfl_sync(0xffffffffu, base, 0);
                if (p) {
                    int pos = base + __popc(m & ((1u << lane) - 1u));
                    if (pos < MAXDEG) g_col[i * MAXDEG + pos] = j;
                }
            }
        }
    }
    __syncthreads();
    if (tid == 0) g_deg[i] = cnt < MAXDEG ? cnt : MAXDEG;
}

// ---------------- K2: GEMM1 (TF32, cp.async double-buffered) + scores1 epilogue ----------------
#define GBM 128
#define GBN 128
#define GBK 32
#define LDA (GBK + 4)
#define LDB (GBN + 4)
#define ASZ (GBM * LDA)     // 4608 floats
#define BSZ (GBK * LDB)     // 4224 floats
#define G1_SMEM ((2 * ASZ + 2 * BSZ) * 4)   // 70656 bytes

__global__ void __launch_bounds__(256) gemm1_kernel(const float* __restrict__ x,
                                                    const float* __restrict__ W,
                                                    const float* __restrict__ as1,
                                                    const float* __restrict__ ad1) {
    extern __shared__ float smemf[];
    float* As[2] = { smemf, smemf + ASZ };
    float* Bs[2] = { smemf + 2 * ASZ, smemf + 2 * ASZ + BSZ };

    int bm = blockIdx.y * GBM;
    int bn = blockIdx.x * GBN;
    int tid = threadIdx.x;
    int lane = tid & 31;
    int wid = tid >> 5;
    int wr = wid >> 1;
    int wc = wid & 1;

    wmma::fragment<wmma::accumulator, 16, 16, 8, float> acc[2][4];
    #pragma unroll
    for (int i = 0; i < 2; i++)
        #pragma unroll
        for (int j = 0; j < 4; j++) wmma::fill_fragment(acc[i][j], 0.0f);

    auto stage = [&](int kt, int s) {
        const float* xs = x + (size_t)bm * F_IN + kt * GBK;
        #pragma unroll
        for (int t = tid; t < GBM * 8; t += 256) {
            int r = t >> 3, q = t & 7;
            cp_async16(&As[s][r * LDA + q * 4], xs + (size_t)r * F_IN + q * 4);
        }
        const float* ws = W + (size_t)kt * GBK * D1 + bn;
        #pragma unroll
        for (int t = tid; t < GBK * 32; t += 256) {
            int r = t >> 5, q = t & 31;
            cp_async16(&Bs[s][r * LDB + q * 4], ws + (size_t)r * D1 + q * 4);
        }
        cp_commit();
    };

    stage(0, 0);
    const int NKT = F_IN / GBK;   // 16
    for (int kt = 0; kt < NKT; kt++) {
        int cur = kt & 1;
        if (kt + 1 < NKT) { stage(kt + 1, cur ^ 1); cp_wait<1>(); }
        else              { cp_wait<0>(); }
        __syncthreads();

        #pragma unroll
        for (int ks = 0; ks < GBK / 8; ks++) {
            wmma::fragment<wmma::matrix_a, 16, 16, 8, wmma::precision::tf32, wmma::row_major> a[2];
            wmma::fragment<wmma::matrix_b, 16, 16, 8, wmma::precision::tf32, wmma::row_major> b[4];
            #pragma unroll
            for (int i = 0; i < 2; i++) {
                wmma::load_matrix_sync(a[i], &As[cur][(wr * 32 + i * 16) * LDA + ks * 8], LDA);
                #pragma unroll
                for (int e = 0; e < a[i].num_elements; e++)
                    a[i].x[e] = wmma::__float_to_tf32(a[i].x[e]);
            }
            #pragma unroll
            for (int j = 0; j < 4; j++) {
                wmma::load_matrix_sync(b[j], &Bs[cur][ks * 8 * LDB + wc * 64 + j * 16], LDB);
                #pragma unroll
                for (int e = 0; e < b[j].num_elements; e++)
                    b[j].x[e] = wmma::__float_to_tf32(b[j].x[e]);
            }
            #pragma unroll
            for (int i = 0; i < 2; i++)
                #pragma unroll
                for (int j = 0; j < 4; j++)
                    wmma::mma_sync(acc[i][j], a[i], b[j], acc[i][j]);
        }
        __syncthreads();
    }

    #pragma unroll
    for (int i = 0; i < 2; i++)
        #pragma unroll
        for (int j = 0; j < 4; j++)
            wmma::store_matrix_sync(&g_h1[(size_t)(bm + wr * 32 + i * 16) * D1 + bn + wc * 64 + j * 16],
                                    acc[i][j], D1, wmma::mem_row_major);
    __syncthreads();   // make all g_h1 tile writes visible block-wide

    // fused scores1 epilogue: this block owns heads h0, h0+1 fully (128 cols)
    {
        int h0 = bn >> 6;              // 2 heads per 128-col block
        int lhalf = lane >> 4;         // 0 -> head h0, 1 -> head h0+1
        int l16 = lane & 15;
        float4 vs = *(const float4*)(as1 + (h0 + lhalf) * HC + l16 * 4);
        float4 vd = *(const float4*)(ad1 + (h0 + lhalf) * HC + l16 * 4);
        #pragma unroll
        for (int rr = 0; rr < 16; rr++) {
            int n = bm + wid * 16 + rr;
            float4 v = *(const float4*)(g_h1 + (size_t)n * D1 + bn + lane * 4);
            float ss = v.x * vs.x + v.y * vs.y + v.z * vs.z + v.w * vs.w;
            float dd = v.x * vd.x + v.y * vd.y + v.z * vd.z + v.w * vd.w;
            #pragma unroll
            for (int o = 1; o < 16; o <<= 1) {
                ss += __shfl_xor_sync(0xffffffffu, ss, o);
                dd += __shfl_xor_sync(0xffffffffu, dd, o);
            }
            if (l16 == 0) {
                g_asrc1[n * NH + h0 + lhalf] = ss;
                g_adst1[n * NH + h0 + lhalf] = dd;
            }
        }
    }
}

// ---------------- K4: layer-1 sparse attention + bias + ELU ----------------
__global__ void attn1_kernel(const float* __restrict__ b1) {
    int i = blockIdx.x;
    int tid = threadIdx.x;
    int h = tid >> 5;
    int lane = tid & 31;

    __shared__ int   nbr[MAXDEG];
    __shared__ float wgt[NH][MAXDEG];
    __shared__ int   s_deg;
    if (tid == 0) s_deg = g_deg[i];
    __syncthreads();
    int deg = s_deg;
    for (int j = tid; j < deg; j += 256) nbr[j] = g_col[i * MAXDEG + j];
    __syncthreads();

    float adst = g_adst1[i * NH + h];

    float m = -1e30f;
    for (int j = lane; j < deg; j += 32) {
        float a = g_asrc1[nbr[j] * NH + h] + adst;
        a = a > 0.0f ? a : 0.2f * a;
        wgt[h][j] = a;
        m = fmaxf(m, a);
    }
    #pragma unroll
    for (int o = 16; o; o >>= 1) m = fmaxf(m, __shfl_xor_sync(0xffffffffu, m, o));

    float s = 0.0f;
    for (int j = lane; j < deg; j += 32) {
        float e = expf(wgt[h][j] - m);
        wgt[h][j] = e;
        s += e;
    }
    #pragma unroll
    for (int o = 16; o; o >>= 1) s += __shfl_xor_sync(0xffffffffu, s, o);
    float inv = 1.0f / s;
    __syncwarp();

    // gather: 2 neighbors per iter; 16 lanes x float4 per neighbor
    int grp = lane >> 4, l16 = lane & 15;
    float4 acc = make_float4(0.f, 0.f, 0.f, 0.f);
    for (int j = 0; j < deg; j += 2) {
        int jj = j + grp;
        float w = (jj < deg) ? wgt[h][jj] : 0.0f;
        int nb = nbr[(jj < deg) ? jj : 0];
        float4 v = *(const float4*)(g_h1 + (size_t)nb * D1 + h * HC + l16 * 4);
        acc.x = fmaf(w, v.x, acc.x);
        acc.y = fmaf(w, v.y, acc.y);
        acc.z = fmaf(w, v.z, acc.z);
        acc.w = fmaf(w, v.w, acc.w);
    }
    acc.x += __shfl_xor_sync(0xffffffffu, acc.x, 16);
    acc.y += __shfl_xor_sync(0xffffffffu, acc.y, 16);
    acc.z += __shfl_xor_sync(0xffffffffu, acc.z, 16);
    acc.w += __shfl_xor_sync(0xffffffffu, acc.w, 16);

    if (grp == 0) {
        int c0 = h * HC + l16 * 4;
        float4 bb = *(const float4*)(b1 + c0);
        float y0 = acc.x * inv + bb.x;
        float y1 = acc.y * inv + bb.y;
        float y2 = acc.z * inv + bb.z;
        float y3 = acc.w * inv + bb.w;
        float4 r;
        r.x = y0 > 0.0f ? y0 : expm1f(y0);
        r.y = y1 > 0.0f ? y1 : expm1f(y1);
        r.z = y2 > 0.0f ? y2 : expm1f(y2);
        r.w = y3 > 0.0f ? y3 : expm1f(y3);
        *(float4*)(g_e1 + (size_t)i * D1 + c0) = r;
    }
}

// ---------------- K5: GEMM2 + fused scores2 ----------------
__global__ void gemm2_kernel(const float* __restrict__ W2,
                             const float* __restrict__ as2,
                             const float* __restrict__ ad2) {
    __shared__ float sW[D1 * 17];
    int tid = threadIdx.x;
    int wid = tid >> 5;
    int lane = tid & 31;
    for (int t = tid; t < D1 * NC2; t += 256) {
        int k = t >> 4, c = t & 15;
        sW[k * 17 + c] = W2[t];
    }
    __syncthreads();

    int row = blockIdx.x * 8 + wid;
    const float* e = g_e1 + (size_t)row * D1;
    float p[NC2];
    #pragma unroll
    for (int c = 0; c < NC2; c++) p[c] = 0.0f;
    #pragma unroll 2
    for (int k = lane; k < D1; k += 32) {
        float v = e[k];
        const float* w = &sW[k * 17];
        #pragma unroll
        for (int c = 0; c < NC2; c++) p[c] = fmaf(v, w[c], p[c]);
    }
    #pragma unroll
    for (int c = 0; c < NC2; c++) {
        #pragma unroll
        for (int o = 16; o; o >>= 1) p[c] += __shfl_xor_sync(0xffffffffu, p[c], o);
    }
    if (lane == 0) {
        float s = 0.0f, d = 0.0f;
        #pragma unroll
        for (int c = 0; c < NC2; c++) {
            g_h2[(size_t)row * NC2 + c] = p[c];
            s = fmaf(p[c], as2[c], s);
            d = fmaf(p[c], ad2[c], d);
        }
        g_a2s[row] = s;
        g_a2d[row] = d;
    }
}

// ---------------- K7: layer-2 sparse attention -> output (8 rows/block) ----------------
__global__ void attn2_kernel(const float* __restrict__ b2, float* __restrict__ out) {
    int tid = threadIdx.x;
    int wid = tid >> 5;
    int lane = tid & 31;
    int i = blockIdx.x * 8 + wid;

    __shared__ int   nbr[8][MAXDEG];
    __shared__ float wgt[8][MAXDEG];
    int deg = g_deg[i];
    for (int j = lane; j < deg; j += 32) nbr[wid][j] = g_col[i * MAXDEG + j];
    __syncwarp();

    float adst = g_a2d[i];
    float m = -1e30f;
    for (int j = lane; j < deg; j += 32) {
        float a = g_a2s[nbr[wid][j]] + adst;
        a = a > 0.0f ? a : 0.2f * a;
        wgt[wid][j] = a;
        m = fmaxf(m, a);
    }
    #pragma unroll
    for (int o = 16; o; o >>= 1) m = fmaxf(m, __shfl_xor_sync(0xffffffffu, m, o));
    float s = 0.0f;
    for (int j = lane; j < deg; j += 32) {
        float e = expf(wgt[wid][j] - m);
        wgt[wid][j] = e;
        s += e;
    }
    #pragma unroll
    for (int o = 16; o; o >>= 1) s += __shfl_xor_sync(0xffffffffu, s, o);
    float inv = 1.0f / s;
    __syncwarp();

    // gather: 8 neighbors per iter; 4 lanes x float4 per neighbor
    int grp = lane >> 2, l4 = lane & 3;
    float4 acc = make_float4(0.f, 0.f, 0.f, 0.f);
    for (int j = 0; j < deg; j += 8) {
        int jj = j + grp;
        float w = (jj < deg) ? wgt[wid][jj] : 0.0f;
        int nb = nbr[wid][(jj < deg) ? jj : 0];
        float4 v = *(const float4*)(g_h2 + (size_t)nb * NC2 + l4 * 4);
        acc.x = fmaf(w, v.x, acc.x);
        acc.y = fmaf(w, v.y, acc.y);
        acc.z = fmaf(w, v.z, acc.z);
        acc.w = fmaf(w, v.w, acc.w);
    }
    #pragma unroll
    for (int o = 4; o < 32; o <<= 1) {
        acc.x += __shfl_xor_sync(0xffffffffu, acc.x, o);
        acc.y += __shfl_xor_sync(0xffffffffu, acc.y, o);
        acc.z += __shfl_xor_sync(0xffffffffu, acc.z, o);
        acc.w += __shfl_xor_sync(0xffffffffu, acc.w, o);
    }
    if (lane < 4) {
        float4 bb = *(const float4*)(b2 + lane * 4);
        float4 r;
        r.x = acc.x * inv + bb.x;
        r.y = acc.y * inv + bb.y;
        r.z = acc.z * inv + bb.z;
        r.w = acc.w * inv + bb.w;
        *(float4*)(out + (size_t)i * NC2 + lane * 4) = r;
    }
}

// ---------------- launch ----------------
extern "C" void kernel_launch(void* const* d_in, const int* in_sizes, int n_in,
                              void* d_out, int out_size) {
    const float* x   = (const float*)d_in[0];
    const float* adj = (const float*)d_in[1];
    const float* W1  = (const float*)d_in[2];
    const float* as1 = (const float*)d_in[3];
    const float* ad1 = (const float*)d_in[4];
    const float* b1  = (const float*)d_in[5];
    const float* W2  = (const float*)d_in[6];
    const float* as2 = (const float*)d_in[7];
    const float* ad2 = (const float*)d_in[8];
    const float* b2  = (const float*)d_in[9];
    float* out = (float*)d_out;

    static cudaStream_t s2 = 0;
    static cudaEvent_t evFork = 0, evJoin = 0;
    static bool init = false;
    if (!init) {
        cudaFuncSetAttribute(gemm1_kernel, cudaFuncAttributeMaxDynamicSharedMemorySize, G1_SMEM);
        if (cudaStreamCreateWithFlags(&s2, cudaStreamNonBlocking) != cudaSuccess) s2 = 0;
        if (cudaEventCreateWithFlags(&evFork, cudaEventDisableTiming) != cudaSuccess) evFork = 0;
        if (cudaEventCreateWithFlags(&evJoin, cudaEventDisableTiming) != cudaSuccess) evJoin = 0;
        if (!evFork || !evJoin) s2 = 0;
        init = true;
    }

    dim3 g1(D1 / GBN, N_NODES / GBM);   // (4, 32)

    if (s2) {
        cudaEventRecord(evFork, 0);
        cudaStreamWaitEvent(s2, evFork, 0);
        build_adj_kernel<<<N_NODES, 256, 0, s2>>>(adj);
        gemm1_kernel<<<g1, 256, G1_SMEM>>>(x, W1, as1, ad1);
        cudaEventRecord(evJoin, s2);
        cudaStreamWaitEvent(0, evJoin, 0);
    } else {
        build_adj_kernel<<<N_NODES, 256>>>(adj);
        gemm1_kernel<<<g1, 256, G1_SMEM>>>(x, W1, as1, ad1);
    }

    attn1_kernel<<<N_NODES, 256>>>(b1);
    gemm2_kernel<<<N_NODES / 8, 256>>>(W2, as2, ad2);
    attn2_kernel<<<N_NODES / 8, 256>>>(b2, out);
}